// round 10
// baseline (speedup 1.0000x reference)
#include <cuda_runtime.h>
#include <cstdint>

// ---------------------------------------------------------------------------
// GCN: out = segment_sum(feature[src], dst) @ W^T + b
// R10: counting-sort pipeline + c-parity-packed f32x2 GEMM (packs on W only,
// F pairs free via 64-bit broadcast LDS) + shfl-broadcast MLP reduce.
// ---------------------------------------------------------------------------

#define MAX_NODES 50000
#define MAX_EDGES 625000
#define DIM 128
#define HALF_K 64
#define C2 (HALF_K / 2)       // 32 c-pairs per half
#define TILE_ROWS 64
#define SCAN_BLK 256
#define NUM_SCAN_BLOCKS ((MAX_NODES + SCAN_BLK - 1) / SCAN_BLK)  // 196

__device__ float g_feat2[(size_t)MAX_NODES * DIM];  // 25.6 MB transformed feats
__device__ int   g_src[MAX_EDGES];
__device__ int   g_dst[MAX_EDGES];
__device__ int   g_esrc[MAX_EDGES];                 // src ids sorted by dst
__device__ int   g_count[MAX_NODES];
__device__ int   g_off[MAX_NODES + 1];
__device__ int   g_cursor[MAX_NODES];
__device__ int   g_bsum[NUM_SCAN_BLOCKS];
__device__ int   g_boff[NUM_SCAN_BLOCKS];
__device__ int   g_idx_is_64;

// packed f32x2 FMA: d = a*b + c on both 32-bit halves
#define FMA2(d, a, b, c) \
    asm("fma.rn.f32x2 %0, %1, %2, %3;" : "=l"(d) : "l"(a), "l"(b), "l"(c))
// pack two distinct floats into one b64
#define PACKAB(d, a, b) \
    asm("mov.b64 %0, {%1, %2};" : "=l"(d) : "r"(__float_as_uint(a)), "r"(__float_as_uint(b)))
// unpack b64 -> two floats
#define UNPACK2(lo, hi, v) \
    asm("mov.b64 {%0, %1}, %2;" : "=r"(lo), "=r"(hi) : "l"(v))

// ---------------------------------------------------------------------------
// Fused: zero counts (all blocks) + index-width detect (block 0, warp 0).
// int64 indices => odd 32-bit words (high words) all zero.
// ---------------------------------------------------------------------------
__global__ __launch_bounds__(256) void zero_detect_kernel(
    const int* __restrict__ a, const int* __restrict__ b)
{
    int i = blockIdx.x * blockDim.x + threadIdx.x;
    if (i < MAX_NODES) g_count[i] = 0;
    if (blockIdx.x == 0 && threadIdx.x < 32) {
        int lane = threadIdx.x;
        int nonzero = 0;
        for (int j = 2 * lane + 1; j < 2048; j += 64)
            if (a[j] != 0 || b[j] != 0) nonzero = 1;
        unsigned any = __any_sync(0xFFFFFFFFu, nonzero);
        if (lane == 0) g_idx_is_64 = any ? 0 : 1;
    }
}

// ---------------------------------------------------------------------------
// Normalize indices to int scratch + histogram of dst.
// ---------------------------------------------------------------------------
__global__ __launch_bounds__(256) void normalize_hist_kernel(
    const int* __restrict__ src_words, const int* __restrict__ dst_words, int E)
{
    int i = blockIdx.x * blockDim.x + threadIdx.x;
    if (i >= E) return;
    int is64 = g_idx_is_64;
    int s = is64 ? src_words[2 * i] : src_words[i];
    int d = is64 ? dst_words[2 * i] : dst_words[i];
    g_src[i] = s;
    g_dst[i] = d;
    if ((unsigned)d < MAX_NODES && (unsigned)s < MAX_NODES)
        atomicAdd(&g_count[d], 1);
}

// ---------------------------------------------------------------------------
// Scan stage 1: per-block exclusive scan of 256 counts; block sum to g_bsum.
// ---------------------------------------------------------------------------
__global__ __launch_bounds__(SCAN_BLK) void scan1_kernel()
{
    __shared__ int sp[SCAN_BLK];
    int t = threadIdx.x;
    int i = blockIdx.x * SCAN_BLK + t;
    int v = (i < MAX_NODES) ? g_count[i] : 0;
    sp[t] = v;
    __syncthreads();
    #pragma unroll
    for (int d = 1; d < SCAN_BLK; d <<= 1) {
        int u = (t >= d) ? sp[t - d] : 0;
        __syncthreads();
        sp[t] += u;
        __syncthreads();
    }
    if (i < MAX_NODES) g_off[i] = sp[t] - v;
    if (t == SCAN_BLK - 1) g_bsum[blockIdx.x] = sp[t];
}

// ---------------------------------------------------------------------------
// Scan stage 2: single CTA scans the 196 block sums.
// ---------------------------------------------------------------------------
__global__ __launch_bounds__(SCAN_BLK) void scan2_kernel()
{
    __shared__ int sp[SCAN_BLK];
    int t = threadIdx.x;
    int v = (t < NUM_SCAN_BLOCKS) ? g_bsum[t] : 0;
    sp[t] = v;
    __syncthreads();
    #pragma unroll
    for (int d = 1; d < SCAN_BLK; d <<= 1) {
        int u = (t >= d) ? sp[t - d] : 0;
        __syncthreads();
        sp[t] += u;
        __syncthreads();
    }
    if (t < NUM_SCAN_BLOCKS) g_boff[t] = sp[t] - v;
    if (t == SCAN_BLK - 1) g_off[MAX_NODES] = sp[t];
}

// ---------------------------------------------------------------------------
// Scan stage 3: add block offsets; materialize g_off and g_cursor.
// ---------------------------------------------------------------------------
__global__ __launch_bounds__(256) void scan3_kernel()
{
    int i = blockIdx.x * blockDim.x + threadIdx.x;
    if (i >= MAX_NODES) return;
    int v = g_off[i] + g_boff[i >> 8];
    g_off[i] = v;
    g_cursor[i] = v;
}

// ---------------------------------------------------------------------------
// Bucket fill: place each edge's src into its dst bucket.
// ---------------------------------------------------------------------------
__global__ __launch_bounds__(256) void fill_kernel(int E)
{
    int i = blockIdx.x * blockDim.x + threadIdx.x;
    if (i >= E) return;
    int s = g_src[i];
    int d = g_dst[i];
    if ((unsigned)d >= MAX_NODES || (unsigned)s >= MAX_NODES) return;
    int pos = atomicAdd(&g_cursor[d], 1);
    g_esrc[pos] = s;
}

// ---------------------------------------------------------------------------
// GEMM: feat2[n][k] = sum_c feature[n][c] * W[k][c]
// c-parity f32x2 packing: acc[r][kq] = (sum over even c, sum over odd c).
// Per c-pair per warp: 2 LDS.128 (W planes) + 4 mov.b64 packs + 8 LDS.64
// (broadcast F pairs) + 32 FFMA2. Epilogue folds lo+hi.
// ---------------------------------------------------------------------------
__global__ __launch_bounds__(256) void gemm_kernel(
    const float* __restrict__ feature, const float* __restrict__ W, int N)
{
    __shared__ float sWe[C2 * DIM];          // sWe[c2*128 + k] = W[k][h*64+2c2]
    __shared__ float sWo[C2 * DIM];          // sWo[c2*128 + k] = W[k][h*64+2c2+1]
    __shared__ float sF[TILE_ROWS * HALF_K]; // row-major feature half-tile

    int tid = threadIdx.x;
    int warp = tid >> 5, lane = tid & 31;
    int row0 = blockIdx.x * TILE_ROWS;
    int r0 = warp * 8;

    unsigned long long acc[8][4];
    #pragma unroll
    for (int r = 0; r < 8; r++)
        #pragma unroll
        for (int q = 0; q < 4; q++) acc[r][q] = 0ULL;

    #pragma unroll
    for (int h = 0; h < 2; h++) {
        if (h) __syncthreads();

        // Load + split W half into even/odd-c planes
        for (int i = tid; i < DIM * HALF_K; i += 256) {
            int k = i >> 6, cl = i & 63;
            float v = W[k * DIM + h * HALF_K + cl];
            int c2 = cl >> 1;
            if (cl & 1) sWo[c2 * DIM + k] = v;
            else        sWe[c2 * DIM + k] = v;
        }
        // Load feature half-tile (float4 coalesced)
        for (int i = tid; i < TILE_ROWS * (HALF_K / 4); i += 256) {
            int r = i >> 4, c4 = i & 15;
            int gr = row0 + r;
            float4 v = make_float4(0.f, 0.f, 0.f, 0.f);
            if (gr < N)
                v = reinterpret_cast<const float4*>(feature + (size_t)gr * DIM + h * HALF_K)[c4];
            reinterpret_cast<float4*>(sF + r * HALF_K)[c4] = v;
        }
        __syncthreads();

        #pragma unroll 4
        for (int c2 = 0; c2 < C2; c2++) {
            float4 we = reinterpret_cast<const float4*>(sWe + c2 * DIM)[lane];
            float4 wo = reinterpret_cast<const float4*>(sWo + c2 * DIM)[lane];
            unsigned long long wp0, wp1, wp2, wp3;
            PACKAB(wp0, we.x, wo.x);
            PACKAB(wp1, we.y, wo.y);
            PACKAB(wp2, we.z, wo.z);
            PACKAB(wp3, we.w, wo.w);
            #pragma unroll
            for (int r = 0; r < 8; r++) {
                // (f_{2c2}, f_{2c2+1}) : contiguous pair, 64-bit broadcast LDS
                unsigned long long fp =
                    *reinterpret_cast<const unsigned long long*>(sF + (r0 + r) * HALF_K + 2 * c2);
                FMA2(acc[r][0], fp, wp0, acc[r][0]);
                FMA2(acc[r][1], fp, wp1, acc[r][1]);
                FMA2(acc[r][2], fp, wp2, acc[r][2]);
                FMA2(acc[r][3], fp, wp3, acc[r][3]);
            }
        }
    }

    // Epilogue: fold even/odd partial sums, store float4 per lane
    #pragma unroll
    for (int r = 0; r < 8; r++) {
        int gr = row0 + r0 + r;
        if (gr < N) {
            float4 o;
            unsigned lo, hi;
            UNPACK2(lo, hi, acc[r][0]); o.x = __uint_as_float(lo) + __uint_as_float(hi);
            UNPACK2(lo, hi, acc[r][1]); o.y = __uint_as_float(lo) + __uint_as_float(hi);
            UNPACK2(lo, hi, acc[r][2]); o.z = __uint_as_float(lo) + __uint_as_float(hi);
            UNPACK2(lo, hi, acc[r][3]); o.w = __uint_as_float(lo) + __uint_as_float(hi);
            reinterpret_cast<float4*>(g_feat2 + (size_t)gr * DIM)[lane] = o;
        }
    }
}

// ---------------------------------------------------------------------------
// Reduce: one warp per node. Indices for the node loaded in ONE coalesced LDG
// (32/warp), broadcast via shfl; gathers run 8-deep for MLP. No atomics.
// ---------------------------------------------------------------------------
__global__ __launch_bounds__(256) void reduce_kernel(
    const float* __restrict__ b, float* __restrict__ out, int N)
{
    int n = (blockIdx.x * blockDim.x + threadIdx.x) >> 5;
    int lane = threadIdx.x & 31;
    if (n >= N) return;

    int begin = g_off[n];
    int end   = g_off[n + 1];

    float4 acc = reinterpret_cast<const float4*>(b)[lane];  // bias seed

    for (int base = begin; base < end; base += 32) {
        int cnt = min(32, end - base);
        int idx = (lane < cnt) ? g_esrc[base + lane] : 0;

        int j = 0;
        for (; j + 8 <= cnt; j += 8) {
            int s0 = __shfl_sync(0xFFFFFFFFu, idx, j + 0);
            int s1 = __shfl_sync(0xFFFFFFFFu, idx, j + 1);
            int s2 = __shfl_sync(0xFFFFFFFFu, idx, j + 2);
            int s3 = __shfl_sync(0xFFFFFFFFu, idx, j + 3);
            int s4 = __shfl_sync(0xFFFFFFFFu, idx, j + 4);
            int s5 = __shfl_sync(0xFFFFFFFFu, idx, j + 5);
            int s6 = __shfl_sync(0xFFFFFFFFu, idx, j + 6);
            int s7 = __shfl_sync(0xFFFFFFFFu, idx, j + 7);
            float4 v0 = reinterpret_cast<const float4*>(g_feat2 + (size_t)s0 * DIM)[lane];
            float4 v1 = reinterpret_cast<const float4*>(g_feat2 + (size_t)s1 * DIM)[lane];
            float4 v2 = reinterpret_cast<const float4*>(g_feat2 + (size_t)s2 * DIM)[lane];
            float4 v3 = reinterpret_cast<const float4*>(g_feat2 + (size_t)s3 * DIM)[lane];
            float4 v4 = reinterpret_cast<const float4*>(g_feat2 + (size_t)s4 * DIM)[lane];
            float4 v5 = reinterpret_cast<const float4*>(g_feat2 + (size_t)s5 * DIM)[lane];
            float4 v6 = reinterpret_cast<const float4*>(g_feat2 + (size_t)s6 * DIM)[lane];
            float4 v7 = reinterpret_cast<const float4*>(g_feat2 + (size_t)s7 * DIM)[lane];
            acc.x += v0.x; acc.y += v0.y; acc.z += v0.z; acc.w += v0.w;
            acc.x += v1.x; acc.y += v1.y; acc.z += v1.z; acc.w += v1.w;
            acc.x += v2.x; acc.y += v2.y; acc.z += v2.z; acc.w += v2.w;
            acc.x += v3.x; acc.y += v3.y; acc.z += v3.z; acc.w += v3.w;
            acc.x += v4.x; acc.y += v4.y; acc.z += v4.z; acc.w += v4.w;
            acc.x += v5.x; acc.y += v5.y; acc.z += v5.z; acc.w += v5.w;
            acc.x += v6.x; acc.y += v6.y; acc.z += v6.z; acc.w += v6.w;
            acc.x += v7.x; acc.y += v7.y; acc.z += v7.z; acc.w += v7.w;
        }
        for (; j + 2 <= cnt; j += 2) {
            int s0 = __shfl_sync(0xFFFFFFFFu, idx, j + 0);
            int s1 = __shfl_sync(0xFFFFFFFFu, idx, j + 1);
            float4 v0 = reinterpret_cast<const float4*>(g_feat2 + (size_t)s0 * DIM)[lane];
            float4 v1 = reinterpret_cast<const float4*>(g_feat2 + (size_t)s1 * DIM)[lane];
            acc.x += v0.x; acc.y += v0.y; acc.z += v0.z; acc.w += v0.w;
            acc.x += v1.x; acc.y += v1.y; acc.z += v1.z; acc.w += v1.w;
        }
        for (; j < cnt; j++) {
            int s = __shfl_sync(0xFFFFFFFFu, idx, j);
            float4 v = reinterpret_cast<const float4*>(g_feat2 + (size_t)s * DIM)[lane];
            acc.x += v.x; acc.y += v.y; acc.z += v.z; acc.w += v.w;
        }
    }
    reinterpret_cast<float4*>(out + (size_t)n * DIM)[lane] = acc;
}

// ---------------------------------------------------------------------------
extern "C" void kernel_launch(void* const* d_in, const int* in_sizes, int n_in,
                              void* d_out, int out_size)
{
    // Identify inputs BY SIZE (robust to ordering and width reporting).
    const float* feature = nullptr;
    const float* W = nullptr;
    const float* b = nullptr;
    const int*   idx_words[2] = {nullptr, nullptr};
    int n_idx = 0;

    for (int i = 0; i < n_in; i++) {
        long long s = in_sizes[i];
        if (s == 128 || s == 512) {
            b = (const float*)d_in[i];
        } else if (s == 16384 || s == 65536) {
            W = (const float*)d_in[i];
        } else if (s == 625000 || s == 1250000 || s == 2500000 || s == 5000000) {
            if (n_idx < 2) idx_words[n_idx++] = (const int*)d_in[i];
        } else if (s == 6400000 || s == 25600000) {
            feature = (const float*)d_in[i];
        }
    }
    if (!feature || !W || !b || n_idx < 2) {  // positional fallback
        feature      = (const float*)d_in[0];
        idx_words[0] = (const int*)d_in[1];
        idx_words[1] = (const int*)d_in[2];
        W            = (const float*)d_in[3];
        b            = (const float*)d_in[4];
    }

    const int N = MAX_NODES;
    const int E = MAX_EDGES;
    float* out = (float*)d_out;

    // [0] zero counts + width detect (fused)
    zero_detect_kernel<<<(N + 255) / 256, 256>>>(idx_words[0], idx_words[1]);
    // [1] normalize + histogram
    normalize_hist_kernel<<<(E + 255) / 256, 256>>>(idx_words[0], idx_words[1], E);
    // [2] scan stage 1
    scan1_kernel<<<NUM_SCAN_BLOCKS, SCAN_BLK>>>();
    // [3] GEMM (independent; placed here for ncu capture-window visibility)
    gemm_kernel<<<(N + TILE_ROWS - 1) / TILE_ROWS, 256>>>(feature, W, N);
    // [4][5] scan stages 2+3
    scan2_kernel<<<1, SCAN_BLK>>>();
    scan3_kernel<<<(N + 255) / 256, 256>>>();
    // [6] bucket fill
    fill_kernel<<<(E + 255) / 256, 256>>>(E);
    // [7] atomic-free segmented reduction + bias
    reduce_kernel<<<(N * 32 + 255) / 256, 256>>>(b, out, N);
}

// round 11
// speedup vs baseline: 1.3731x; 1.3731x over previous
#include <cuda_runtime.h>
#include <cstdint>

// ---------------------------------------------------------------------------
// GCN: out = segment_sum(feature[src], dst) @ W^T + b
// R11: f32x2 GEMM reverted (fma.rn.f32x2 is EMULATED on sm_100a: alu-pipe
// movs + 120 regs -> 115.8us measured). New scalar GEMM register-blocks W
// per 8-column chunk (issue ratio 1.09 per FFMA vs 1.28) with a lane-major
// padded smem layout for conflict-free LDS.128. Keep R10 shfl-MLP reduce
// (~30us) and counting-sort chain (~20us).
// ---------------------------------------------------------------------------

#define MAX_NODES 50000
#define MAX_EDGES 625000
#define DIM 128
#define TILE_ROWS 64
#define SCAN_BLK 256
#define NUM_SCAN_BLOCKS ((MAX_NODES + SCAN_BLK - 1) / SCAN_BLK)  // 196

// W smem: 32 lane-blocks of (4 k-rows x 128 c + 4 pad) = 516 words.
// Lane stride 516 % 32 banks = 4 -> 8-lane LDS.128 phases hit banks
// {4i..4i+3}, conflict-free. 516*4B is 16B-aligned.
#define W_LANE_STRIDE 516
#define W_SMEM_WORDS (32 * W_LANE_STRIDE)            // 16512
#define GEMM_SMEM_BYTES ((W_SMEM_WORDS + TILE_ROWS * DIM) * 4)  // 98816

__device__ float g_feat2[(size_t)MAX_NODES * DIM];  // 25.6 MB transformed feats
__device__ int   g_src[MAX_EDGES];
__device__ int   g_dst[MAX_EDGES];
__device__ int   g_esrc[MAX_EDGES];                 // src ids sorted by dst
__device__ int   g_count[MAX_NODES];
__device__ int   g_off[MAX_NODES + 1];
__device__ int   g_cursor[MAX_NODES];
__device__ int   g_bsum[NUM_SCAN_BLOCKS];
__device__ int   g_boff[NUM_SCAN_BLOCKS];
__device__ int   g_idx_is_64;

// ---------------------------------------------------------------------------
// Fused: zero counts (all blocks) + index-width detect (block 0, warp 0).
// ---------------------------------------------------------------------------
__global__ __launch_bounds__(256) void zero_detect_kernel(
    const int* __restrict__ a, const int* __restrict__ b)
{
    int i = blockIdx.x * blockDim.x + threadIdx.x;
    if (i < MAX_NODES) g_count[i] = 0;
    if (blockIdx.x == 0 && threadIdx.x < 32) {
        int lane = threadIdx.x;
        int nonzero = 0;
        for (int j = 2 * lane + 1; j < 2048; j += 64)
            if (a[j] != 0 || b[j] != 0) nonzero = 1;
        unsigned any = __any_sync(0xFFFFFFFFu, nonzero);
        if (lane == 0) g_idx_is_64 = any ? 0 : 1;
    }
}

// ---------------------------------------------------------------------------
// Normalize indices to int scratch + histogram of dst.
// ---------------------------------------------------------------------------
__global__ __launch_bounds__(256) void normalize_hist_kernel(
    const int* __restrict__ src_words, const int* __restrict__ dst_words, int E)
{
    int i = blockIdx.x * blockDim.x + threadIdx.x;
    if (i >= E) return;
    int is64 = g_idx_is_64;
    int s = is64 ? src_words[2 * i] : src_words[i];
    int d = is64 ? dst_words[2 * i] : dst_words[i];
    g_src[i] = s;
    g_dst[i] = d;
    if ((unsigned)d < MAX_NODES && (unsigned)s < MAX_NODES)
        atomicAdd(&g_count[d], 1);
}

// ---------------------------------------------------------------------------
// Scan stages 1-3 (multi-CTA; validated 4.7us in R8/R9).
// ---------------------------------------------------------------------------
__global__ __launch_bounds__(SCAN_BLK) void scan1_kernel()
{
    __shared__ int sp[SCAN_BLK];
    int t = threadIdx.x;
    int i = blockIdx.x * SCAN_BLK + t;
    int v = (i < MAX_NODES) ? g_count[i] : 0;
    sp[t] = v;
    __syncthreads();
    #pragma unroll
    for (int d = 1; d < SCAN_BLK; d <<= 1) {
        int u = (t >= d) ? sp[t - d] : 0;
        __syncthreads();
        sp[t] += u;
        __syncthreads();
    }
    if (i < MAX_NODES) g_off[i] = sp[t] - v;
    if (t == SCAN_BLK - 1) g_bsum[blockIdx.x] = sp[t];
}

__global__ __launch_bounds__(SCAN_BLK) void scan2_kernel()
{
    __shared__ int sp[SCAN_BLK];
    int t = threadIdx.x;
    int v = (t < NUM_SCAN_BLOCKS) ? g_bsum[t] : 0;
    sp[t] = v;
    __syncthreads();
    #pragma unroll
    for (int d = 1; d < SCAN_BLK; d <<= 1) {
        int u = (t >= d) ? sp[t - d] : 0;
        __syncthreads();
        sp[t] += u;
        __syncthreads();
    }
    if (t < NUM_SCAN_BLOCKS) g_boff[t] = sp[t] - v;
    if (t == SCAN_BLK - 1) g_off[MAX_NODES] = sp[t];
}

__global__ __launch_bounds__(256) void scan3_kernel()
{
    int i = blockIdx.x * blockDim.x + threadIdx.x;
    if (i >= MAX_NODES) return;
    int v = g_off[i] + g_boff[i >> 8];
    g_off[i] = v;
    g_cursor[i] = v;
}

// ---------------------------------------------------------------------------
// Bucket fill: place each edge's src into its dst bucket.
// ---------------------------------------------------------------------------
__global__ __launch_bounds__(256) void fill_kernel(int E)
{
    int i = blockIdx.x * blockDim.x + threadIdx.x;
    if (i >= E) return;
    int s = g_src[i];
    int d = g_dst[i];
    if ((unsigned)d >= MAX_NODES || (unsigned)s >= MAX_NODES) return;
    int pos = atomicAdd(&g_cursor[d], 1);
    g_esrc[pos] = s;
}

// ---------------------------------------------------------------------------
// GEMM: feat2[n][k] = sum_c feature[n][c] * W[k][c]
// 256 threads, 64 rows/CTA. Lane owns k = 4*lane..4*lane+3.
// Per 8-col chunk: 8 LDS.128 (W -> 32 regs, reused by 8 rows) +
// per row 2 broadcast LDS.128 (F) + 32 FFMA. 280 issues / 256 FFMA.
// Single W+F smem load, ONE syncthreads, 16 chunks.
// ---------------------------------------------------------------------------
__global__ __launch_bounds__(256) void gemm_kernel(
    const float* __restrict__ feature, const float* __restrict__ W, int N)
{
    extern __shared__ float smem[];
    float* sW = smem;                 // lane-major padded W, 16512 words
    float* sF = smem + W_SMEM_WORDS;  // [64][128] row-major

    int tid = threadIdx.x;
    int warp = tid >> 5, lane = tid & 31;
    int row0 = blockIdx.x * TILE_ROWS;
    int r0 = warp * 8;

    // Load W into lane-major padded layout (global read coalesced)
    for (int i = tid; i < DIM * DIM; i += 256) {
        int k = i >> 7, c = i & 127;
        sW[(k >> 2) * W_LANE_STRIDE + (k & 3) * DIM + c] = W[i];
    }
    // Load feature tile (float4 coalesced)
    for (int i = tid; i < TILE_ROWS * (DIM / 4); i += 256) {
        int r = i >> 5, c4 = i & 31;
        int gr = row0 + r;
        float4 v = make_float4(0.f, 0.f, 0.f, 0.f);
        if (gr < N) v = reinterpret_cast<const float4*>(feature)[(size_t)gr * 32 + c4];
        reinterpret_cast<float4*>(sF + r * DIM)[c4] = v;
    }
    __syncthreads();

    float4 acc[8];
    #pragma unroll
    for (int r = 0; r < 8; r++) acc[r] = make_float4(0.f, 0.f, 0.f, 0.f);

    const float* wbase = sW + lane * W_LANE_STRIDE;

    #pragma unroll 2
    for (int c0 = 0; c0 < DIM; c0 += 8) {
        // W chunk -> registers: 4 k-rows x 8 c (conflict-free LDS.128)
        float4 wA[4], wB[4];
        #pragma unroll
        for (int q = 0; q < 4; q++) {
            wA[q] = *reinterpret_cast<const float4*>(wbase + q * DIM + c0);
            wB[q] = *reinterpret_cast<const float4*>(wbase + q * DIM + c0 + 4);
        }
        #pragma unroll
        for (int r = 0; r < 8; r++) {
            const float* frow = sF + (r0 + r) * DIM + c0;
            float4 fA = *reinterpret_cast<const float4*>(frow);      // broadcast
            float4 fB = *reinterpret_cast<const float4*>(frow + 4);  // broadcast
            acc[r].x += fA.x * wA[0].x + fA.y * wA[0].y + fA.z * wA[0].z + fA.w * wA[0].w
                      + fB.x * wB[0].x + fB.y * wB[0].y + fB.z * wB[0].z + fB.w * wB[0].w;
            acc[r].y += fA.x * wA[1].x + fA.y * wA[1].y + fA.z * wA[1].z + fA.w * wA[1].w
                      + fB.x * wB[1].x + fB.y * wB[1].y + fB.z * wB[1].z + fB.w * wB[1].w;
            acc[r].z += fA.x * wA[2].x + fA.y * wA[2].y + fA.z * wA[2].z + fA.w * wA[2].w
                      + fB.x * wB[2].x + fB.y * wB[2].y + fB.z * wB[2].z + fB.w * wB[2].w;
            acc[r].w += fA.x * wA[3].x + fA.y * wA[3].y + fA.z * wA[3].z + fA.w * wA[3].w
                      + fB.x * wB[3].x + fB.y * wB[3].y + fB.z * wB[3].z + fB.w * wB[3].w;
        }
    }

    // Store: lane's float4 = k 4*lane..4*lane+3
    #pragma unroll
    for (int r = 0; r < 8; r++) {
        int gr = row0 + r0 + r;
        if (gr < N)
            reinterpret_cast<float4*>(g_feat2 + (size_t)gr * DIM)[lane] = acc[r];
    }
}

// ---------------------------------------------------------------------------
// Reduce: one warp per node. Indices loaded coalesced (32/warp, one LDG),
// shfl-broadcast; gathers run 8-deep for MLP. No atomics. (R10, ~30us)
// ---------------------------------------------------------------------------
__global__ __launch_bounds__(256) void reduce_kernel(
    const float* __restrict__ b, float* __restrict__ out, int N)
{
    int n = (blockIdx.x * blockDim.x + threadIdx.x) >> 5;
    int lane = threadIdx.x & 31;
    if (n >= N) return;

    int begin = g_off[n];
    int end   = g_off[n + 1];

    float4 acc = reinterpret_cast<const float4*>(b)[lane];  // bias seed

    for (int base = begin; base < end; base += 32) {
        int cnt = min(32, end - base);
        int idx = (lane < cnt) ? g_esrc[base + lane] : 0;

        int j = 0;
        for (; j + 8 <= cnt; j += 8) {
            int s0 = __shfl_sync(0xFFFFFFFFu, idx, j + 0);
            int s1 = __shfl_sync(0xFFFFFFFFu, idx, j + 1);
            int s2 = __shfl_sync(0xFFFFFFFFu, idx, j + 2);
            int s3 = __shfl_sync(0xFFFFFFFFu, idx, j + 3);
            int s4 = __shfl_sync(0xFFFFFFFFu, idx, j + 4);
            int s5 = __shfl_sync(0xFFFFFFFFu, idx, j + 5);
            int s6 = __shfl_sync(0xFFFFFFFFu, idx, j + 6);
            int s7 = __shfl_sync(0xFFFFFFFFu, idx, j + 7);
            float4 v0 = reinterpret_cast<const float4*>(g_feat2 + (size_t)s0 * DIM)[lane];
            float4 v1 = reinterpret_cast<const float4*>(g_feat2 + (size_t)s1 * DIM)[lane];
            float4 v2 = reinterpret_cast<const float4*>(g_feat2 + (size_t)s2 * DIM)[lane];
            float4 v3 = reinterpret_cast<const float4*>(g_feat2 + (size_t)s3 * DIM)[lane];
            float4 v4 = reinterpret_cast<const float4*>(g_feat2 + (size_t)s4 * DIM)[lane];
            float4 v5 = reinterpret_cast<const float4*>(g_feat2 + (size_t)s5 * DIM)[lane];
            float4 v6 = reinterpret_cast<const float4*>(g_feat2 + (size_t)s6 * DIM)[lane];
            float4 v7 = reinterpret_cast<const float4*>(g_feat2 + (size_t)s7 * DIM)[lane];
            acc.x += v0.x; acc.y += v0.y; acc.z += v0.z; acc.w += v0.w;
            acc.x += v1.x; acc.y += v1.y; acc.z += v1.z; acc.w += v1.w;
            acc.x += v2.x; acc.y += v2.y; acc.z += v2.z; acc.w += v2.w;
            acc.x += v3.x; acc.y += v3.y; acc.z += v3.z; acc.w += v3.w;
            acc.x += v4.x; acc.y += v4.y; acc.z += v4.z; acc.w += v4.w;
            acc.x += v5.x; acc.y += v5.y; acc.z += v5.z; acc.w += v5.w;
            acc.x += v6.x; acc.y += v6.y; acc.z += v6.z; acc.w += v6.w;
            acc.x += v7.x; acc.y += v7.y; acc.z += v7.z; acc.w += v7.w;
        }
        for (; j + 2 <= cnt; j += 2) {
            int s0 = __shfl_sync(0xFFFFFFFFu, idx, j + 0);
            int s1 = __shfl_sync(0xFFFFFFFFu, idx, j + 1);
            float4 v0 = reinterpret_cast<const float4*>(g_feat2 + (size_t)s0 * DIM)[lane];
            float4 v1 = reinterpret_cast<const float4*>(g_feat2 + (size_t)s1 * DIM)[lane];
            acc.x += v0.x; acc.y += v0.y; acc.z += v0.z; acc.w += v0.w;
            acc.x += v1.x; acc.y += v1.y; acc.z += v1.z; acc.w += v1.w;
        }
        for (; j < cnt; j++) {
            int s = __shfl_sync(0xFFFFFFFFu, idx, j);
            float4 v = reinterpret_cast<const float4*>(g_feat2 + (size_t)s * DIM)[lane];
            acc.x += v.x; acc.y += v.y; acc.z += v.z; acc.w += v.w;
        }
    }
    reinterpret_cast<float4*>(out + (size_t)n * DIM)[lane] = acc;
}

// ---------------------------------------------------------------------------
extern "C" void kernel_launch(void* const* d_in, const int* in_sizes, int n_in,
                              void* d_out, int out_size)
{
    // Identify inputs BY SIZE (robust to ordering and width reporting).
    const float* feature = nullptr;
    const float* W = nullptr;
    const float* b = nullptr;
    const int*   idx_words[2] = {nullptr, nullptr};
    int n_idx = 0;

    for (int i = 0; i < n_in; i++) {
        long long s = in_sizes[i];
        if (s == 128 || s == 512) {
            b = (const float*)d_in[i];
        } else if (s == 16384 || s == 65536) {
            W = (const float*)d_in[i];
        } else if (s == 625000 || s == 1250000 || s == 2500000 || s == 5000000) {
            if (n_idx < 2) idx_words[n_idx++] = (const int*)d_in[i];
        } else if (s == 6400000 || s == 25600000) {
            feature = (const float*)d_in[i];
        }
    }
    if (!feature || !W || !b || n_idx < 2) {  // positional fallback
        feature      = (const float*)d_in[0];
        idx_words[0] = (const int*)d_in[1];
        idx_words[1] = (const int*)d_in[2];
        W            = (const float*)d_in[3];
        b            = (const float*)d_in[4];
    }

    const int N = MAX_NODES;
    const int E = MAX_EDGES;
    float* out = (float*)d_out;

    // Opt-in to >48KB dynamic smem. Host-side, idempotent; the first
    // (non-captured) correctness call sets it persistently.
    cudaFuncSetAttribute(gemm_kernel,
                         cudaFuncAttributeMaxDynamicSharedMemorySize,
                         GEMM_SMEM_BYTES);

    zero_detect_kernel<<<(N + 255) / 256, 256>>>(idx_words[0], idx_words[1]);
    normalize_hist_kernel<<<(E + 255) / 256, 256>>>(idx_words[0], idx_words[1], E);
    scan1_kernel<<<NUM_SCAN_BLOCKS, SCAN_BLK>>>();
    gemm_kernel<<<(N + TILE_ROWS - 1) / TILE_ROWS, 256, GEMM_SMEM_BYTES>>>(feature, W, N);
    scan2_kernel<<<1, SCAN_BLK>>>();
    scan3_kernel<<<(N + 255) / 256, 256>>>();
    fill_kernel<<<(E + 255) / 256, 256>>>(E);
    reduce_kernel<<<(N * 32 + 255) / 256, 256>>>(b, out, N);
}

// round 12
// speedup vs baseline: 1.4730x; 1.0727x over previous
#include <cuda_runtime.h>
#include <cstdint>

// ---------------------------------------------------------------------------
// GCN: out = segment_sum(feature[src], dst) @ W^T + b
// R12: GEMM moved to tensor cores — mma.sync.m16n8k8 TF32 with 3xTF32 split
// (A_hi*B_hi + A_hi*B_lo + A_lo*B_hi) for fp32-grade accuracy. smem tiles
// padded to stride 132 for conflict-free fragment gathers. Counting-sort
// chain and shfl-MLP reduce unchanged (validated R10/R11).
// ---------------------------------------------------------------------------

#define MAX_NODES 50000
#define MAX_EDGES 625000
#define DIM 128
#define TILE_ROWS 64
#define SCAN_BLK 256
#define NUM_SCAN_BLOCKS ((MAX_NODES + SCAN_BLK - 1) / SCAN_BLK)  // 196

#define PAD_STRIDE 132            // 128 + 4 pad: frag gather bank = lane%32
#define SMEM_A_WORDS (TILE_ROWS * PAD_STRIDE)   // 8448
#define SMEM_W_WORDS (DIM * PAD_STRIDE)         // 16896
#define GEMM_SMEM_BYTES ((SMEM_A_WORDS + SMEM_W_WORDS) * 4)  // 101376

__device__ float g_feat2[(size_t)MAX_NODES * DIM];  // 25.6 MB transformed feats
__device__ int   g_src[MAX_EDGES];
__device__ int   g_dst[MAX_EDGES];
__device__ int   g_esrc[MAX_EDGES];                 // src ids sorted by dst
__device__ int   g_count[MAX_NODES];
__device__ int   g_off[MAX_NODES + 1];
__device__ int   g_cursor[MAX_NODES];
__device__ int   g_bsum[NUM_SCAN_BLOCKS];
__device__ int   g_boff[NUM_SCAN_BLOCKS];
__device__ int   g_idx_is_64;

// tf32 round (RNA) of an f32, result as raw b32 bits
__device__ __forceinline__ unsigned tf32_hi(float x)
{
    unsigned u;
    asm("cvt.rna.tf32.f32 %0, %1;" : "=r"(u) : "f"(x));
    return u;
}

// D += A*B, m16n8k8 tf32 (row.col), fp32 accumulate
#define MMA_TF32(d, a0, a1, a2, a3, b0, b1)                                  \
    asm("mma.sync.aligned.m16n8k8.row.col.f32.tf32.tf32.f32 "                \
        "{%0,%1,%2,%3}, {%4,%5,%6,%7}, {%8,%9}, {%0,%1,%2,%3};"              \
        : "+f"(d[0]), "+f"(d[1]), "+f"(d[2]), "+f"(d[3])                     \
        : "r"(a0), "r"(a1), "r"(a2), "r"(a3), "r"(b0), "r"(b1))

// ---------------------------------------------------------------------------
// Fused: zero counts (all blocks) + index-width detect (block 0, warp 0).
// ---------------------------------------------------------------------------
__global__ __launch_bounds__(256) void zero_detect_kernel(
    const int* __restrict__ a, const int* __restrict__ b)
{
    int i = blockIdx.x * blockDim.x + threadIdx.x;
    if (i < MAX_NODES) g_count[i] = 0;
    if (blockIdx.x == 0 && threadIdx.x < 32) {
        int lane = threadIdx.x;
        int nonzero = 0;
        for (int j = 2 * lane + 1; j < 2048; j += 64)
            if (a[j] != 0 || b[j] != 0) nonzero = 1;
        unsigned any = __any_sync(0xFFFFFFFFu, nonzero);
        if (lane == 0) g_idx_is_64 = any ? 0 : 1;
    }
}

// ---------------------------------------------------------------------------
// Normalize indices to int scratch + histogram of dst.
// ---------------------------------------------------------------------------
__global__ __launch_bounds__(256) void normalize_hist_kernel(
    const int* __restrict__ src_words, const int* __restrict__ dst_words, int E)
{
    int i = blockIdx.x * blockDim.x + threadIdx.x;
    if (i >= E) return;
    int is64 = g_idx_is_64;
    int s = is64 ? src_words[2 * i] : src_words[i];
    int d = is64 ? dst_words[2 * i] : dst_words[i];
    g_src[i] = s;
    g_dst[i] = d;
    if ((unsigned)d < MAX_NODES && (unsigned)s < MAX_NODES)
        atomicAdd(&g_count[d], 1);
}

// ---------------------------------------------------------------------------
// Scan stages 1-3 (multi-CTA; validated ~5us).
// ---------------------------------------------------------------------------
__global__ __launch_bounds__(SCAN_BLK) void scan1_kernel()
{
    __shared__ int sp[SCAN_BLK];
    int t = threadIdx.x;
    int i = blockIdx.x * SCAN_BLK + t;
    int v = (i < MAX_NODES) ? g_count[i] : 0;
    sp[t] = v;
    __syncthreads();
    #pragma unroll
    for (int d = 1; d < SCAN_BLK; d <<= 1) {
        int u = (t >= d) ? sp[t - d] : 0;
        __syncthreads();
        sp[t] += u;
        __syncthreads();
    }
    if (i < MAX_NODES) g_off[i] = sp[t] - v;
    if (t == SCAN_BLK - 1) g_bsum[blockIdx.x] = sp[t];
}

__global__ __launch_bounds__(SCAN_BLK) void scan2_kernel()
{
    __shared__ int sp[SCAN_BLK];
    int t = threadIdx.x;
    int v = (t < NUM_SCAN_BLOCKS) ? g_bsum[t] : 0;
    sp[t] = v;
    __syncthreads();
    #pragma unroll
    for (int d = 1; d < SCAN_BLK; d <<= 1) {
        int u = (t >= d) ? sp[t - d] : 0;
        __syncthreads();
        sp[t] += u;
        __syncthreads();
    }
    if (t < NUM_SCAN_BLOCKS) g_boff[t] = sp[t] - v;
    if (t == SCAN_BLK - 1) g_off[MAX_NODES] = sp[t];
}

__global__ __launch_bounds__(256) void scan3_kernel()
{
    int i = blockIdx.x * blockDim.x + threadIdx.x;
    if (i >= MAX_NODES) return;
    int v = g_off[i] + g_boff[i >> 8];
    g_off[i] = v;
    g_cursor[i] = v;
}

// ---------------------------------------------------------------------------
// Bucket fill.
// ---------------------------------------------------------------------------
__global__ __launch_bounds__(256) void fill_kernel(int E)
{
    int i = blockIdx.x * blockDim.x + threadIdx.x;
    if (i >= E) return;
    int s = g_src[i];
    int d = g_dst[i];
    if ((unsigned)d >= MAX_NODES || (unsigned)s >= MAX_NODES) return;
    int pos = atomicAdd(&g_cursor[d], 1);
    g_esrc[pos] = s;
}

// ---------------------------------------------------------------------------
// Tensor-core GEMM: feat2[m][n] = sum_k feature[m][k] * W[n][k]
// CTA: 64 rows x 128 cols, 8 warps. Warps 0-3: n in [0,64); 4-7: n in [64,128).
// Warp m-block = (warp&3)*16. Per k-step (k8): load A frag (4 LDS) + 8 B
// frags (2 LDS each), split hi/lo, 3 MMAs per n-tile.
// ---------------------------------------------------------------------------
__global__ __launch_bounds__(256) void gemm_tc_kernel(
    const float* __restrict__ feature, const float* __restrict__ W, int N)
{
    extern __shared__ float smem[];
    float* sA = smem;                  // [64][132]
    float* sW = smem + SMEM_A_WORDS;   // [128][132], sW[n*132+k] = W[n][k]

    int tid = threadIdx.x;
    int warp = tid >> 5, lane = tid & 31;
    int row0 = blockIdx.x * TILE_ROWS;

    // Load W (coalesced float4; stride-132 rows stay 16B-aligned)
    for (int i = tid; i < DIM * (DIM / 4); i += 256) {
        int n = i >> 5, c4 = i & 31;
        float4 v = reinterpret_cast<const float4*>(W + n * DIM)[c4];
        *reinterpret_cast<float4*>(sW + n * PAD_STRIDE + c4 * 4) = v;
    }
    // Load A tile (zero-padded at the tail)
    for (int i = tid; i < TILE_ROWS * (DIM / 4); i += 256) {
        int r = i >> 5, c4 = i & 31;
        int gr = row0 + r;
        float4 v = make_float4(0.f, 0.f, 0.f, 0.f);
        if (gr < N) v = reinterpret_cast<const float4*>(feature)[(size_t)gr * 32 + c4];
        *reinterpret_cast<float4*>(sA + r * PAD_STRIDE + c4 * 4) = v;
    }
    __syncthreads();

    int mrow = (warp & 3) * 16;        // warp's 16-row block
    int ncol0 = (warp >> 2) * 64;      // warp's N half
    int g = lane >> 2;                 // group id (0..7)
    int t = lane & 3;                  // thread-in-group (0..3)

    float acc[8][4];
    #pragma unroll
    for (int nt = 0; nt < 8; nt++)
        #pragma unroll
        for (int q = 0; q < 4; q++) acc[nt][q] = 0.f;

    #pragma unroll 2
    for (int k0 = 0; k0 < DIM; k0 += 8) {
        // A fragment: a0=(g,t) a1=(g+8,t) a2=(g,t+4) a3=(g+8,t+4)
        float a0 = sA[(mrow + g) * PAD_STRIDE + k0 + t];
        float a1 = sA[(mrow + g + 8) * PAD_STRIDE + k0 + t];
        float a2 = sA[(mrow + g) * PAD_STRIDE + k0 + t + 4];
        float a3 = sA[(mrow + g + 8) * PAD_STRIDE + k0 + t + 4];
        unsigned ah0 = tf32_hi(a0), ah1 = tf32_hi(a1);
        unsigned ah2 = tf32_hi(a2), ah3 = tf32_hi(a3);
        unsigned al0 = __float_as_uint(a0 - __uint_as_float(ah0));
        unsigned al1 = __float_as_uint(a1 - __uint_as_float(ah1));
        unsigned al2 = __float_as_uint(a2 - __uint_as_float(ah2));
        unsigned al3 = __float_as_uint(a3 - __uint_as_float(ah3));

        #pragma unroll
        for (int nt = 0; nt < 8; nt++) {
            int n0 = ncol0 + nt * 8;
            // B fragment (col layout): b0=(k=t,n=g) b1=(k=t+4,n=g)
            float b0 = sW[(n0 + g) * PAD_STRIDE + k0 + t];
            float b1 = sW[(n0 + g) * PAD_STRIDE + k0 + t + 4];
            unsigned bh0 = tf32_hi(b0), bh1 = tf32_hi(b1);
            unsigned bl0 = __float_as_uint(b0 - __uint_as_float(bh0));
            unsigned bl1 = __float_as_uint(b1 - __uint_as_float(bh1));

            MMA_TF32(acc[nt], ah0, ah1, ah2, ah3, bh0, bh1);  // hi*hi
            MMA_TF32(acc[nt], ah0, ah1, ah2, ah3, bl0, bl1);  // hi*lo
            MMA_TF32(acc[nt], al0, al1, al2, al3, bh0, bh1);  // lo*hi
        }
    }

    // Store: c0,c1 -> (row g, cols 2t,2t+1); c2,c3 -> (row g+8, same cols)
    int gr0 = row0 + mrow + g;
    int gr1 = gr0 + 8;
    #pragma unroll
    for (int nt = 0; nt < 8; nt++) {
        int col = ncol0 + nt * 8 + t * 2;
        if (gr0 < N) {
            float2 v = make_float2(acc[nt][0], acc[nt][1]);
            *reinterpret_cast<float2*>(g_feat2 + (size_t)gr0 * DIM + col) = v;
        }
        if (gr1 < N) {
            float2 v = make_float2(acc[nt][2], acc[nt][3]);
            *reinterpret_cast<float2*>(g_feat2 + (size_t)gr1 * DIM + col) = v;
        }
    }
}

// ---------------------------------------------------------------------------
// Reduce: one warp per node, coalesced index load + shfl broadcast, 8-deep
// gather MLP, single store with bias seed. No atomics. (validated ~30us)
// ---------------------------------------------------------------------------
__global__ __launch_bounds__(256) void reduce_kernel(
    const float* __restrict__ b, float* __restrict__ out, int N)
{
    int n = (blockIdx.x * blockDim.x + threadIdx.x) >> 5;
    int lane = threadIdx.x & 31;
    if (n >= N) return;

    int begin = g_off[n];
    int end   = g_off[n + 1];

    float4 acc = reinterpret_cast<const float4*>(b)[lane];  // bias seed

    for (int base = begin; base < end; base += 32) {
        int cnt = min(32, end - base);
        int idx = (lane < cnt) ? g_esrc[base + lane] : 0;

        int j = 0;
        for (; j + 8 <= cnt; j += 8) {
            int s0 = __shfl_sync(0xFFFFFFFFu, idx, j + 0);
            int s1 = __shfl_sync(0xFFFFFFFFu, idx, j + 1);
            int s2 = __shfl_sync(0xFFFFFFFFu, idx, j + 2);
            int s3 = __shfl_sync(0xFFFFFFFFu, idx, j + 3);
            int s4 = __shfl_sync(0xFFFFFFFFu, idx, j + 4);
            int s5 = __shfl_sync(0xFFFFFFFFu, idx, j + 5);
            int s6 = __shfl_sync(0xFFFFFFFFu, idx, j + 6);
            int s7 = __shfl_sync(0xFFFFFFFFu, idx, j + 7);
            float4 v0 = reinterpret_cast<const float4*>(g_feat2 + (size_t)s0 * DIM)[lane];
            float4 v1 = reinterpret_cast<const float4*>(g_feat2 + (size_t)s1 * DIM)[lane];
            float4 v2 = reinterpret_cast<const float4*>(g_feat2 + (size_t)s2 * DIM)[lane];
            float4 v3 = reinterpret_cast<const float4*>(g_feat2 + (size_t)s3 * DIM)[lane];
            float4 v4 = reinterpret_cast<const float4*>(g_feat2 + (size_t)s4 * DIM)[lane];
            float4 v5 = reinterpret_cast<const float4*>(g_feat2 + (size_t)s5 * DIM)[lane];
            float4 v6 = reinterpret_cast<const float4*>(g_feat2 + (size_t)s6 * DIM)[lane];
            float4 v7 = reinterpret_cast<const float4*>(g_feat2 + (size_t)s7 * DIM)[lane];
            acc.x += v0.x; acc.y += v0.y; acc.z += v0.z; acc.w += v0.w;
            acc.x += v1.x; acc.y += v1.y; acc.z += v1.z; acc.w += v1.w;
            acc.x += v2.x; acc.y += v2.y; acc.z += v2.z; acc.w += v2.w;
            acc.x += v3.x; acc.y += v3.y; acc.z += v3.z; acc.w += v3.w;
            acc.x += v4.x; acc.y += v4.y; acc.z += v4.z; acc.w += v4.w;
            acc.x += v5.x; acc.y += v5.y; acc.z += v5.z; acc.w += v5.w;
            acc.x += v6.x; acc.y += v6.y; acc.z += v6.z; acc.w += v6.w;
            acc.x += v7.x; acc.y += v7.y; acc.z += v7.z; acc.w += v7.w;
        }
        for (; j + 2 <= cnt; j += 2) {
            int s0 = __shfl_sync(0xFFFFFFFFu, idx, j + 0);
            int s1 = __shfl_sync(0xFFFFFFFFu, idx, j + 1);
            float4 v0 = reinterpret_cast<const float4*>(g_feat2 + (size_t)s0 * DIM)[lane];
            float4 v1 = reinterpret_cast<const float4*>(g_feat2 + (size_t)s1 * DIM)[lane];
            acc.x += v0.x; acc.y += v0.y; acc.z += v0.z; acc.w += v0.w;
            acc.x += v1.x; acc.y += v1.y; acc.z += v1.z; acc.w += v1.w;
        }
        for (; j < cnt; j++) {
            int s = __shfl_sync(0xFFFFFFFFu, idx, j);
            float4 v = reinterpret_cast<const float4*>(g_feat2 + (size_t)s * DIM)[lane];
            acc.x += v.x; acc.y += v.y; acc.z += v.z; acc.w += v.w;
        }
    }
    reinterpret_cast<float4*>(out + (size_t)n * DIM)[lane] = acc;
}

// ---------------------------------------------------------------------------
extern "C" void kernel_launch(void* const* d_in, const int* in_sizes, int n_in,
                              void* d_out, int out_size)
{
    // Identify inputs BY SIZE (robust to ordering and width reporting).
    const float* feature = nullptr;
    const float* W = nullptr;
    const float* b = nullptr;
    const int*   idx_words[2] = {nullptr, nullptr};
    int n_idx = 0;

    for (int i = 0; i < n_in; i++) {
        long long s = in_sizes[i];
        if (s == 128 || s == 512) {
            b = (const float*)d_in[i];
        } else if (s == 16384 || s == 65536) {
            W = (const float*)d_in[i];
        } else if (s == 625000 || s == 1250000 || s == 2500000 || s == 5000000) {
            if (n_idx < 2) idx_words[n_idx++] = (const int*)d_in[i];
        } else if (s == 6400000 || s == 25600000) {
            feature = (const float*)d_in[i];
        }
    }
    if (!feature || !W || !b || n_idx < 2) {  // positional fallback
        feature      = (const float*)d_in[0];
        idx_words[0] = (const int*)d_in[1];
        idx_words[1] = (const int*)d_in[2];
        W            = (const float*)d_in[3];
        b            = (const float*)d_in[4];
    }

    const int N = MAX_NODES;
    const int E = MAX_EDGES;
    float* out = (float*)d_out;

    cudaFuncSetAttribute(gemm_tc_kernel,
                         cudaFuncAttributeMaxDynamicSharedMemorySize,
                         GEMM_SMEM_BYTES);

    zero_detect_kernel<<<(N + 255) / 256, 256>>>(idx_words[0], idx_words[1]);
    normalize_hist_kernel<<<(E + 255) / 256, 256>>>(idx_words[0], idx_words[1], E);
    scan1_kernel<<<NUM_SCAN_BLOCKS, SCAN_BLK>>>();
    gemm_tc_kernel<<<(N + TILE_ROWS - 1) / TILE_ROWS, 256, GEMM_SMEM_BYTES>>>(feature, W, N);
    scan2_kernel<<<1, SCAN_BLK>>>();
    scan3_kernel<<<(N + 255) / 256, 256>>>();
    fill_kernel<<<(E + 255) / 256, 256>>>(E);
    reduce_kernel<<<(N * 32 + 255) / 256, 256>>>(b, out, N);
}

// round 13
// speedup vs baseline: 1.6534x; 1.1224x over previous
#include <cuda_runtime.h>
#include <cstdint>

// ---------------------------------------------------------------------------
// GCN: out = segment_sum(feature[src], dst) @ W^T + b
// R13: TC GEMM smem halved via k-split double-pass (51KB -> 4 CTAs/SM,
// occ 22.7%->~50%). R12 was latency-bound at 2 CTAs/SM, not issue-bound.
// 3xTF32 split + fragment maps unchanged (validated rel_err 1e-6).
// Counting-sort chain + shfl-MLP reduce unchanged.
// ---------------------------------------------------------------------------

#define MAX_NODES 50000
#define MAX_EDGES 625000
#define DIM 128
#define KH 64                     // k-half width
#define TILE_ROWS 64
#define SCAN_BLK 256
#define NUM_SCAN_BLOCKS ((MAX_NODES + SCAN_BLK - 1) / SCAN_BLK)  // 196

#define PAD_STRIDE 68             // 64 + 4 pad: frag gather bank = 4g+t, CF
#define SMEM_A_WORDS (TILE_ROWS * PAD_STRIDE)   // 4352
#define SMEM_W_WORDS (DIM * PAD_STRIDE)         // 8704
#define GEMM_SMEM_BYTES ((SMEM_A_WORDS + SMEM_W_WORDS) * 4)  // 52224

__device__ float g_feat2[(size_t)MAX_NODES * DIM];  // 25.6 MB transformed feats
__device__ int   g_src[MAX_EDGES];
__device__ int   g_dst[MAX_EDGES];
__device__ int   g_esrc[MAX_EDGES];                 // src ids sorted by dst
__device__ int   g_count[MAX_NODES];
__device__ int   g_off[MAX_NODES + 1];
__device__ int   g_cursor[MAX_NODES];
__device__ int   g_bsum[NUM_SCAN_BLOCKS];
__device__ int   g_boff[NUM_SCAN_BLOCKS];
__device__ int   g_idx_is_64;

// tf32 round (RNA) of an f32, result as raw b32 bits
__device__ __forceinline__ unsigned tf32_hi(float x)
{
    unsigned u;
    asm("cvt.rna.tf32.f32 %0, %1;" : "=r"(u) : "f"(x));
    return u;
}

// D += A*B, m16n8k8 tf32 (row.col), fp32 accumulate
#define MMA_TF32(d, a0, a1, a2, a3, b0, b1)                                  \
    asm("mma.sync.aligned.m16n8k8.row.col.f32.tf32.tf32.f32 "                \
        "{%0,%1,%2,%3}, {%4,%5,%6,%7}, {%8,%9}, {%0,%1,%2,%3};"              \
        : "+f"(d[0]), "+f"(d[1]), "+f"(d[2]), "+f"(d[3])                     \
        : "r"(a0), "r"(a1), "r"(a2), "r"(a3), "r"(b0), "r"(b1))

// ---------------------------------------------------------------------------
// Fused: zero counts (all blocks) + index-width detect (block 0, warp 0).
// ---------------------------------------------------------------------------
__global__ __launch_bounds__(256) void zero_detect_kernel(
    const int* __restrict__ a, const int* __restrict__ b)
{
    int i = blockIdx.x * blockDim.x + threadIdx.x;
    if (i < MAX_NODES) g_count[i] = 0;
    if (blockIdx.x == 0 && threadIdx.x < 32) {
        int lane = threadIdx.x;
        int nonzero = 0;
        for (int j = 2 * lane + 1; j < 2048; j += 64)
            if (a[j] != 0 || b[j] != 0) nonzero = 1;
        unsigned any = __any_sync(0xFFFFFFFFu, nonzero);
        if (lane == 0) g_idx_is_64 = any ? 0 : 1;
    }
}

// ---------------------------------------------------------------------------
// Normalize indices to int scratch + histogram of dst.
// ---------------------------------------------------------------------------
__global__ __launch_bounds__(256) void normalize_hist_kernel(
    const int* __restrict__ src_words, const int* __restrict__ dst_words, int E)
{
    int i = blockIdx.x * blockDim.x + threadIdx.x;
    if (i >= E) return;
    int is64 = g_idx_is_64;
    int s = is64 ? src_words[2 * i] : src_words[i];
    int d = is64 ? dst_words[2 * i] : dst_words[i];
    g_src[i] = s;
    g_dst[i] = d;
    if ((unsigned)d < MAX_NODES && (unsigned)s < MAX_NODES)
        atomicAdd(&g_count[d], 1);
}

// ---------------------------------------------------------------------------
// Scan stages 1-3 (multi-CTA; validated ~5us).
// ---------------------------------------------------------------------------
__global__ __launch_bounds__(SCAN_BLK) void scan1_kernel()
{
    __shared__ int sp[SCAN_BLK];
    int t = threadIdx.x;
    int i = blockIdx.x * SCAN_BLK + t;
    int v = (i < MAX_NODES) ? g_count[i] : 0;
    sp[t] = v;
    __syncthreads();
    #pragma unroll
    for (int d = 1; d < SCAN_BLK; d <<= 1) {
        int u = (t >= d) ? sp[t - d] : 0;
        __syncthreads();
        sp[t] += u;
        __syncthreads();
    }
    if (i < MAX_NODES) g_off[i] = sp[t] - v;
    if (t == SCAN_BLK - 1) g_bsum[blockIdx.x] = sp[t];
}

__global__ __launch_bounds__(SCAN_BLK) void scan2_kernel()
{
    __shared__ int sp[SCAN_BLK];
    int t = threadIdx.x;
    int v = (t < NUM_SCAN_BLOCKS) ? g_bsum[t] : 0;
    sp[t] = v;
    __syncthreads();
    #pragma unroll
    for (int d = 1; d < SCAN_BLK; d <<= 1) {
        int u = (t >= d) ? sp[t - d] : 0;
        __syncthreads();
        sp[t] += u;
        __syncthreads();
    }
    if (t < NUM_SCAN_BLOCKS) g_boff[t] = sp[t] - v;
    if (t == SCAN_BLK - 1) g_off[MAX_NODES] = sp[t];
}

__global__ __launch_bounds__(256) void scan3_kernel()
{
    int i = blockIdx.x * blockDim.x + threadIdx.x;
    if (i >= MAX_NODES) return;
    int v = g_off[i] + g_boff[i >> 8];
    g_off[i] = v;
    g_cursor[i] = v;
}

// ---------------------------------------------------------------------------
// Bucket fill.
// ---------------------------------------------------------------------------
__global__ __launch_bounds__(256) void fill_kernel(int E)
{
    int i = blockIdx.x * blockDim.x + threadIdx.x;
    if (i >= E) return;
    int s = g_src[i];
    int d = g_dst[i];
    if ((unsigned)d >= MAX_NODES || (unsigned)s >= MAX_NODES) return;
    int pos = atomicAdd(&g_cursor[d], 1);
    g_esrc[pos] = s;
}

// ---------------------------------------------------------------------------
// Tensor-core GEMM, k-split: feat2[m][n] = sum_k feature[m][k] * W[n][k]
// CTA: 64 rows x 128 cols, 8 warps. Two k-stages of 64, shared buffers,
// accumulators persist. 51KB smem -> 4 CTAs/SM.
// ---------------------------------------------------------------------------
__global__ __launch_bounds__(256) void gemm_tc_kernel(
    const float* __restrict__ feature, const float* __restrict__ W, int N)
{
    extern __shared__ float smem[];
    float* sA = smem;                  // [64][68]
    float* sW = smem + SMEM_A_WORDS;   // [128][68], sW[n*68+kk] = W[n][h*64+kk]

    int tid = threadIdx.x;
    int warp = tid >> 5, lane = tid & 31;
    int row0 = blockIdx.x * TILE_ROWS;

    int mrow = (warp & 3) * 16;        // warp's 16-row block
    int ncol0 = (warp >> 2) * 64;      // warp's N half
    int g = lane >> 2;                 // group id (0..7)
    int t = lane & 3;                  // thread-in-group (0..3)

    float acc[8][4];
    #pragma unroll
    for (int nt = 0; nt < 8; nt++)
        #pragma unroll
        for (int q = 0; q < 4; q++) acc[nt][q] = 0.f;

    #pragma unroll
    for (int h = 0; h < 2; h++) {
        if (h) __syncthreads();  // protect buffer reuse

        // Load W k-half (float4 coalesced; stride-68 rows stay 16B-aligned)
        for (int i = tid; i < DIM * (KH / 4); i += 256) {
            int n = i >> 4, c4 = i & 15;
            float4 v = reinterpret_cast<const float4*>(W + n * DIM + h * KH)[c4];
            *reinterpret_cast<float4*>(sW + n * PAD_STRIDE + c4 * 4) = v;
        }
        // Load A k-half (zero-padded at row tail)
        for (int i = tid; i < TILE_ROWS * (KH / 4); i += 256) {
            int r = i >> 4, c4 = i & 15;
            int gr = row0 + r;
            float4 v = make_float4(0.f, 0.f, 0.f, 0.f);
            if (gr < N)
                v = reinterpret_cast<const float4*>(feature + (size_t)gr * DIM + h * KH)[c4];
            *reinterpret_cast<float4*>(sA + r * PAD_STRIDE + c4 * 4) = v;
        }
        __syncthreads();

        #pragma unroll 2
        for (int k0 = 0; k0 < KH; k0 += 8) {
            // A fragment: a0=(g,t) a1=(g+8,t) a2=(g,t+4) a3=(g+8,t+4)
            float a0 = sA[(mrow + g) * PAD_STRIDE + k0 + t];
            float a1 = sA[(mrow + g + 8) * PAD_STRIDE + k0 + t];
            float a2 = sA[(mrow + g) * PAD_STRIDE + k0 + t + 4];
            float a3 = sA[(mrow + g + 8) * PAD_STRIDE + k0 + t + 4];
            unsigned ah0 = tf32_hi(a0), ah1 = tf32_hi(a1);
            unsigned ah2 = tf32_hi(a2), ah3 = tf32_hi(a3);
            unsigned al0 = __float_as_uint(a0 - __uint_as_float(ah0));
            unsigned al1 = __float_as_uint(a1 - __uint_as_float(ah1));
            unsigned al2 = __float_as_uint(a2 - __uint_as_float(ah2));
            unsigned al3 = __float_as_uint(a3 - __uint_as_float(ah3));

            #pragma unroll
            for (int nt = 0; nt < 8; nt++) {
                int n0 = ncol0 + nt * 8;
                // B fragment (col layout): b0=(k=t,n=g) b1=(k=t+4,n=g)
                float b0 = sW[(n0 + g) * PAD_STRIDE + k0 + t];
                float b1 = sW[(n0 + g) * PAD_STRIDE + k0 + t + 4];
                unsigned bh0 = tf32_hi(b0), bh1 = tf32_hi(b1);
                unsigned bl0 = __float_as_uint(b0 - __uint_as_float(bh0));
                unsigned bl1 = __float_as_uint(b1 - __uint_as_float(bh1));

                MMA_TF32(acc[nt], ah0, ah1, ah2, ah3, bh0, bh1);  // hi*hi
                MMA_TF32(acc[nt], ah0, ah1, ah2, ah3, bl0, bl1);  // hi*lo
                MMA_TF32(acc[nt], al0, al1, al2, al3, bh0, bh1);  // lo*hi
            }
        }
    }

    // Store: c0,c1 -> (row g, cols 2t,2t+1); c2,c3 -> (row g+8, same cols)
    int gr0 = row0 + mrow + g;
    int gr1 = gr0 + 8;
    #pragma unroll
    for (int nt = 0; nt < 8; nt++) {
        int col = ncol0 + nt * 8 + t * 2;
        if (gr0 < N) {
            float2 v = make_float2(acc[nt][0], acc[nt][1]);
            *reinterpret_cast<float2*>(g_feat2 + (size_t)gr0 * DIM + col) = v;
        }
        if (gr1 < N) {
            float2 v = make_float2(acc[nt][2], acc[nt][3]);
            *reinterpret_cast<float2*>(g_feat2 + (size_t)gr1 * DIM + col) = v;
        }
    }
}

// ---------------------------------------------------------------------------
// Reduce: one warp per node, coalesced index load + shfl broadcast, 8-deep
// gather MLP, single store with bias seed. No atomics. (validated ~30us)
// ---------------------------------------------------------------------------
__global__ __launch_bounds__(256) void reduce_kernel(
    const float* __restrict__ b, float* __restrict__ out, int N)
{
    int n = (blockIdx.x * blockDim.x + threadIdx.x) >> 5;
    int lane = threadIdx.x & 31;
    if (n >= N) return;

    int begin = g_off[n];
    int end   = g_off[n + 1];

    float4 acc = reinterpret_cast<const float4*>(b)[lane];  // bias seed

    for (int base = begin; base < end; base += 32) {
        int cnt = min(32, end - base);
        int idx = (lane < cnt) ? g_esrc[base + lane] : 0;

        int j = 0;
        for (; j + 8 <= cnt; j += 8) {
            int s0 = __shfl_sync(0xFFFFFFFFu, idx, j + 0);
            int s1 = __shfl_sync(0xFFFFFFFFu, idx, j + 1);
            int s2 = __shfl_sync(0xFFFFFFFFu, idx, j + 2);
            int s3 = __shfl_sync(0xFFFFFFFFu, idx, j + 3);
            int s4 = __shfl_sync(0xFFFFFFFFu, idx, j + 4);
            int s5 = __shfl_sync(0xFFFFFFFFu, idx, j + 5);
            int s6 = __shfl_sync(0xFFFFFFFFu, idx, j + 6);
            int s7 = __shfl_sync(0xFFFFFFFFu, idx, j + 7);
            float4 v0 = reinterpret_cast<const float4*>(g_feat2 + (size_t)s0 * DIM)[lane];
            float4 v1 = reinterpret_cast<const float4*>(g_feat2 + (size_t)s1 * DIM)[lane];
            float4 v2 = reinterpret_cast<const float4*>(g_feat2 + (size_t)s2 * DIM)[lane];
            float4 v3 = reinterpret_cast<const float4*>(g_feat2 + (size_t)s3 * DIM)[lane];
            float4 v4 = reinterpret_cast<const float4*>(g_feat2 + (size_t)s4 * DIM)[lane];
            float4 v5 = reinterpret_cast<const float4*>(g_feat2 + (size_t)s5 * DIM)[lane];
            float4 v6 = reinterpret_cast<const float4*>(g_feat2 + (size_t)s6 * DIM)[lane];
            float4 v7 = reinterpret_cast<const float4*>(g_feat2 + (size_t)s7 * DIM)[lane];
            acc.x += v0.x; acc.y += v0.y; acc.z += v0.z; acc.w += v0.w;
            acc.x += v1.x; acc.y += v1.y; acc.z += v1.z; acc.w += v1.w;
            acc.x += v2.x; acc.y += v2.y; acc.z += v2.z; acc.w += v2.w;
            acc.x += v3.x; acc.y += v3.y; acc.z += v3.z; acc.w += v3.w;
            acc.x += v4.x; acc.y += v4.y; acc.z += v4.z; acc.w += v4.w;
            acc.x += v5.x; acc.y += v5.y; acc.z += v5.z; acc.w += v5.w;
            acc.x += v6.x; acc.y += v6.y; acc.z += v6.z; acc.w += v6.w;
            acc.x += v7.x; acc.y += v7.y; acc.z += v7.z; acc.w += v7.w;
        }
        for (; j + 2 <= cnt; j += 2) {
            int s0 = __shfl_sync(0xFFFFFFFFu, idx, j + 0);
            int s1 = __shfl_sync(0xFFFFFFFFu, idx, j + 1);
            float4 v0 = reinterpret_cast<const float4*>(g_feat2 + (size_t)s0 * DIM)[lane];
            float4 v1 = reinterpret_cast<const float4*>(g_feat2 + (size_t)s1 * DIM)[lane];
            acc.x += v0.x; acc.y += v0.y; acc.z += v0.z; acc.w += v0.w;
            acc.x += v1.x; acc.y += v1.y; acc.z += v1.z; acc.w += v1.w;
        }
        for (; j < cnt; j++) {
            int s = __shfl_sync(0xFFFFFFFFu, idx, j);
            float4 v = reinterpret_cast<const float4*>(g_feat2 + (size_t)s * DIM)[lane];
            acc.x += v.x; acc.y += v.y; acc.z += v.z; acc.w += v.w;
        }
    }
    reinterpret_cast<float4*>(out + (size_t)n * DIM)[lane] = acc;
}

// ---------------------------------------------------------------------------
extern "C" void kernel_launch(void* const* d_in, const int* in_sizes, int n_in,
                              void* d_out, int out_size)
{
    // Identify inputs BY SIZE (robust to ordering and width reporting).
    const float* feature = nullptr;
    const float* W = nullptr;
    const float* b = nullptr;
    const int*   idx_words[2] = {nullptr, nullptr};
    int n_idx = 0;

    for (int i = 0; i < n_in; i++) {
        long long s = in_sizes[i];
        if (s == 128 || s == 512) {
            b = (const float*)d_in[i];
        } else if (s == 16384 || s == 65536) {
            W = (const float*)d_in[i];
        } else if (s == 625000 || s == 1250000 || s == 2500000 || s == 5000000) {
            if (n_idx < 2) idx_words[n_idx++] = (const int*)d_in[i];
        } else if (s == 6400000 || s == 25600000) {
            feature = (const float*)d_in[i];
        }
    }
    if (!feature || !W || !b || n_idx < 2) {  // positional fallback
        feature      = (const float*)d_in[0];
        idx_words[0] = (const int*)d_in[1];
        idx_words[1] = (const int*)d_in[2];
        W            = (const float*)d_in[3];
        b            = (const float*)d_in[4];
    }

    const int N = MAX_NODES;
    const int E = MAX_EDGES;
    float* out = (float*)d_out;

    cudaFuncSetAttribute(gemm_tc_kernel,
                         cudaFuncAttributeMaxDynamicSharedMemorySize,
                         GEMM_SMEM_BYTES);

    zero_detect_kernel<<<(N + 255) / 256, 256>>>(idx_words[0], idx_words[1]);
    normalize_hist_kernel<<<(E + 255) / 256, 256>>>(idx_words[0], idx_words[1], E);
    scan1_kernel<<<NUM_SCAN_BLOCKS, SCAN_BLK>>>();
    gemm_tc_kernel<<<(N + TILE_ROWS - 1) / TILE_ROWS, 256, GEMM_SMEM_BYTES>>>(feature, W, N);
    scan2_kernel<<<1, SCAN_BLK>>>();
    scan3_kernel<<<(N + 255) / 256, 256>>>();
    fill_kernel<<<(E + 255) / 256, 256>>>(E);
    reduce_kernel<<<(N * 32 + 255) / 256, 256>>>(b, out, N);
}